// round 1
// baseline (speedup 1.0000x reference)
#include <cuda_runtime.h>
#include <math.h>

// ---------------- problem constants ----------------
#define B_      8192
#define N_      49
#define DIM_    128
#define NH_     4
#define HD_     32
#define NW_     64
#define QKV_N   384
#define M_TOTAL (B_ * N_)          // 401408
#define SCALE_  0.17677669529663687f  // 32^-0.5

// ---------------- scratch (device globals; no allocation allowed) ----------------
__device__ float g_qkv[(size_t)M_TOTAL * QKV_N];   // [B*N, 384]
__device__ float g_obuf[(size_t)M_TOTAL * DIM_];   // [B*N, 128] attention output (head-merged)

// ============================================================================
// Tiled SGEMM: out[m][n] = sum_k X[m][k] * W[n][k] + bias[n]
// M tiles of 64 rows, N tiles of 64 cols, K = 128 (chunks of 32).
// blockDim = (16,16); each thread computes a 4x4 register tile.
// Smem is K-major with +4 pad so compute reads are float4.
// ============================================================================
__global__ void __launch_bounds__(256) gemm_xwT(
    const float* __restrict__ X, const float* __restrict__ W,
    const float* __restrict__ bias, float* __restrict__ out, int Nstride)
{
    __shared__ float As[32][68];   // [k][m], 64 rows of X tile
    __shared__ float Bs[32][68];   // [k][n], 64 rows of W tile

    const int tx = threadIdx.x, ty = threadIdx.y;
    const int tid = ty * 16 + tx;
    const int m0 = blockIdx.x * 64;
    const int n0 = blockIdx.y * 64;

    float acc[4][4] = {};

    #pragma unroll
    for (int kc = 0; kc < 128; kc += 32) {
        // cooperative load: k fastest over tid -> coalesced global reads
        #pragma unroll
        for (int it = 0; it < 8; ++it) {
            int idx = tid + it * 256;          // 0..2047
            int k = idx & 31;
            int m = idx >> 5;                  // 0..63
            As[k][m] = X[(m0 + m) * 128 + kc + k];
            Bs[k][m] = W[(n0 + m) * 128 + kc + k];
        }
        __syncthreads();

        #pragma unroll
        for (int k = 0; k < 32; ++k) {
            float4 a = *(const float4*)&As[k][4 * ty];
            float4 b = *(const float4*)&Bs[k][4 * tx];
            acc[0][0] += a.x * b.x; acc[0][1] += a.x * b.y; acc[0][2] += a.x * b.z; acc[0][3] += a.x * b.w;
            acc[1][0] += a.y * b.x; acc[1][1] += a.y * b.y; acc[1][2] += a.y * b.z; acc[1][3] += a.y * b.w;
            acc[2][0] += a.z * b.x; acc[2][1] += a.z * b.y; acc[2][2] += a.z * b.z; acc[2][3] += a.z * b.w;
            acc[3][0] += a.w * b.x; acc[3][1] += a.w * b.y; acc[3][2] += a.w * b.z; acc[3][3] += a.w * b.w;
        }
        __syncthreads();
    }

    // epilogue: add bias, vectorized store
    const int nb = n0 + 4 * tx;
    float4 bv = *(const float4*)&bias[nb];
    #pragma unroll
    for (int i = 0; i < 4; ++i) {
        float4 r;
        r.x = acc[i][0] + bv.x;
        r.y = acc[i][1] + bv.y;
        r.z = acc[i][2] + bv.z;
        r.w = acc[i][3] + bv.w;
        *(float4*)&out[(size_t)(m0 + 4 * ty + i) * Nstride + nb] = r;
    }
}

// ============================================================================
// Fused window attention: one CTA per window b, 256 threads, 4 heads serial.
// Loads mask[b%64], rpb table once per CTA. Per head: q/k/v -> smem,
// S = scale*qk^T + rpb + mask, softmax (warp per row), O = S@V.
// ============================================================================
__global__ void __launch_bounds__(256) attn_kernel(
    const float* __restrict__ qkv,        // [B*N, 384]
    const float* __restrict__ mask,       // [64, 49, 49]
    const float* __restrict__ rpb,        // [169, 4]
    const int*   __restrict__ relidx,     // [49, 49]
    float*       __restrict__ obuf)       // [B*N, 128]
{
    __shared__ float sm_mask[N_ * N_];        // 2401
    __shared__ float sm_rpb[169 * NH_];       // 676
    __shared__ float sm_q[N_][33];
    __shared__ float sm_k[N_][33];
    __shared__ float sm_v[N_][33];
    __shared__ float sm_S[N_ * N_];           // 2401

    const int b = blockIdx.x;
    const int w = b & (NW_ - 1);
    const int tid = threadIdx.x;
    const int lane = tid & 31;
    const int warp = tid >> 5;

    // load per-window constants
    for (int idx = tid; idx < N_ * N_; idx += 256)
        sm_mask[idx] = mask[w * (N_ * N_) + idx];
    for (int idx = tid; idx < 169 * NH_; idx += 256)
        sm_rpb[idx] = rpb[idx];
    __syncthreads();

    for (int h = 0; h < NH_; ++h) {
        // ---- load q, k, v for this head ----
        for (int idx = tid; idx < N_ * HD_; idx += 256) {
            int i = idx >> 5;
            int d = idx & 31;
            const float* base = qkv + (size_t)(b * N_ + i) * QKV_N + h * HD_;
            sm_q[i][d] = base[d];
            sm_k[i][d] = base[128 + d];
            sm_v[i][d] = base[256 + d];
        }
        __syncthreads();

        // ---- S = scale * q @ k^T + rpb + mask ----
        for (int idx = tid; idx < N_ * N_; idx += 256) {
            int i = idx / N_;
            int j = idx - i * N_;
            float acc = 0.f;
            #pragma unroll
            for (int d = 0; d < HD_; ++d)
                acc += sm_q[i][d] * sm_k[j][d];
            int r = __ldg(&relidx[idx]);
            sm_S[idx] = acc * SCALE_ + sm_rpb[r * NH_ + h] + sm_mask[idx];
        }
        __syncthreads();

        // ---- softmax over rows (one warp per row) ----
        for (int i = warp; i < N_; i += 8) {
            float* row = &sm_S[i * N_];
            float x0 = row[lane];                                  // lane 0..31 always valid (N=49)
            float x1 = (lane + 32 < N_) ? row[lane + 32] : -1e30f; // lanes 0..16
            float m = fmaxf(x0, x1);
            #pragma unroll
            for (int off = 16; off > 0; off >>= 1)
                m = fmaxf(m, __shfl_xor_sync(0xffffffffu, m, off));
            float e0 = __expf(x0 - m);
            float e1 = (lane + 32 < N_) ? __expf(x1 - m) : 0.f;
            float s = e0 + e1;
            #pragma unroll
            for (int off = 16; off > 0; off >>= 1)
                s += __shfl_xor_sync(0xffffffffu, s, off);
            float inv = __frcp_rn(s);
            row[lane] = e0 * inv;
            if (lane + 32 < N_) row[lane + 32] = e1 * inv;
        }
        __syncthreads();

        // ---- O = S @ V ----
        for (int idx = tid; idx < N_ * HD_; idx += 256) {
            int i = idx >> 5;
            int d = idx & 31;
            const float* srow = &sm_S[i * N_];
            float acc = 0.f;
            #pragma unroll
            for (int j = 0; j < N_; ++j)
                acc += srow[j] * sm_v[j][d];
            obuf[(size_t)(b * N_ + i) * DIM_ + h * HD_ + d] = acc;
        }
        __syncthreads();  // protect sm_q/k/v/S before next head overwrites
    }
}

// ============================================================================
// launch
// ============================================================================
extern "C" void kernel_launch(void* const* d_in, const int* in_sizes, int n_in,
                              void* d_out, int out_size)
{
    const float* x      = (const float*)d_in[0];
    const float* mask   = (const float*)d_in[1];
    const float* qkv_w  = (const float*)d_in[2];
    const float* qkv_b  = (const float*)d_in[3];
    const float* proj_w = (const float*)d_in[4];
    const float* proj_b = (const float*)d_in[5];
    const float* rpb    = (const float*)d_in[6];
    const int*   rel    = (const int*)d_in[7];
    float* out = (float*)d_out;

    float* qkv_buf = nullptr;
    float* obuf = nullptr;
    cudaGetSymbolAddress((void**)&qkv_buf, g_qkv);
    cudaGetSymbolAddress((void**)&obuf, g_obuf);

    dim3 blk(16, 16);
    // QKV projection: [401408,128] @ [384,128]^T -> [401408,384]
    gemm_xwT<<<dim3(M_TOTAL / 64, QKV_N / 64), blk>>>(x, qkv_w, qkv_b, qkv_buf, QKV_N);
    // windowed attention
    attn_kernel<<<B_, 256>>>(qkv_buf, mask, rpb, rel, obuf);
    // output projection: [401408,128] @ [128,128]^T -> [401408,128]
    gemm_xwT<<<dim3(M_TOTAL / 64, DIM_ / 64), blk>>>(obuf, proj_w, proj_b, out, DIM_);
}

// round 3
// speedup vs baseline: 1.9762x; 1.9762x over previous
#include <cuda_runtime.h>
#include <cuda_bf16.h>
#include <math.h>
#include <stdint.h>

// ---------------- problem constants ----------------
#define B_      8192
#define N_      49
#define DIM_    128
#define NH_     4
#define HD_     32
#define NW_     64
#define QKV_N   384
#define M_TOTAL (B_ * N_)          // 401408
#define SCALE_  0.17677669529663687f  // 32^-0.5

// ---------------- scratch (device globals; no allocation allowed) ----------------
__device__ float g_qkv[(size_t)M_TOTAL * QKV_N];   // [B*N, 384]
__device__ float g_obuf[(size_t)M_TOTAL * DIM_];   // [B*N, 128]

// ============================================================================
// Split-bf16 tensor-core GEMM:  out[m][n] = sum_k X[m][k]*W[n][k] + bias[n]
// CTA tile 128m x 128n, K chunks of 32.
// fp32 split into (hi,lo) bf16; D += Ah*Bh + Ah*Bl + Al*Bh
// via mma.sync.aligned.m16n8k16.row.col.f32.bf16.bf16.f32 (~1e-5 rel err).
// 8 warps: warp grid 4(m) x 2(n); warp tile 32m x 64n = 2x8 mma tiles.
// ============================================================================

#define MMA16816(d, a, b)                                                     \
  asm volatile(                                                               \
      "mma.sync.aligned.m16n8k16.row.col.f32.bf16.bf16.f32 "                  \
      "{%0,%1,%2,%3}, {%4,%5,%6,%7}, {%8,%9}, {%0,%1,%2,%3};"                 \
      : "+f"(d[0]), "+f"(d[1]), "+f"(d[2]), "+f"(d[3])                        \
      : "r"(a[0]), "r"(a[1]), "r"(a[2]), "r"(a[3]), "r"(b[0]), "r"(b[1]))

__device__ __forceinline__ void cvt_store4(__nv_bfloat16* ph, __nv_bfloat16* pl, float4 v)
{
    float f[4] = {v.x, v.y, v.z, v.w};
    __nv_bfloat16 h[4], l[4];
    #pragma unroll
    for (int i = 0; i < 4; ++i) {
        h[i] = __float2bfloat16(f[i]);
        l[i] = __float2bfloat16(f[i] - __bfloat162float(h[i]));
    }
    *(__nv_bfloat162*)(ph)     = __halves2bfloat162(h[0], h[1]);
    *(__nv_bfloat162*)(ph + 2) = __halves2bfloat162(h[2], h[3]);
    *(__nv_bfloat162*)(pl)     = __halves2bfloat162(l[0], l[1]);
    *(__nv_bfloat162*)(pl + 2) = __halves2bfloat162(l[2], l[3]);
}

__global__ void __launch_bounds__(256) gemm_mma(
    const float* __restrict__ X, const float* __restrict__ W,
    const float* __restrict__ bias, float* __restrict__ out, int Nstride)
{
    // K-chunk = 32, stride padded to 40 bf16 (80B) -> conflict-free frag loads.
    // 16B alignment REQUIRED: accessed through uint32_t*/__nv_bfloat162*.
    __shared__ __align__(16) __nv_bfloat16 Ah[128][40], Al[128][40];
    __shared__ __align__(16) __nv_bfloat16 Bh[128][40], Bl[128][40];

    const int tid  = threadIdx.x;
    const int lane = tid & 31;
    const int warp = tid >> 5;
    const int wm   = warp & 3;      // 0..3 -> 32-row slice
    const int wn   = warp >> 2;     // 0..1 -> 64-col slice
    const int g    = lane >> 2;     // groupID 0..7
    const int t    = lane & 3;      // threadID-in-group 0..3

    const int m0 = blockIdx.y * 128;
    const int n0 = blockIdx.x * 128;

    float acc[2][8][4];
    #pragma unroll
    for (int mt = 0; mt < 2; ++mt)
        #pragma unroll
        for (int nt = 0; nt < 8; ++nt)
            #pragma unroll
            for (int r = 0; r < 4; ++r) acc[mt][nt][r] = 0.f;

    for (int kc = 0; kc < 128; kc += 32) {
        // cooperative load + split-convert: 128 rows x 32 cols for X and W
        #pragma unroll
        for (int r = 0; r < 4; ++r) {
            int idx = tid + r * 256;       // 0..1023
            int row = idx >> 3;            // 0..127
            int c4  = (idx & 7) * 4;       // 0..28
            float4 xv = *(const float4*)&X[(size_t)(m0 + row) * 128 + kc + c4];
            cvt_store4(&Ah[row][c4], &Al[row][c4], xv);
            float4 wv = *(const float4*)&W[(size_t)(n0 + row) * 128 + kc + c4];
            cvt_store4(&Bh[row][c4], &Bl[row][c4], wv);
        }
        __syncthreads();

        #pragma unroll
        for (int ks = 0; ks < 2; ++ks) {
            const int col = ks * 16 + 2 * t;
            uint32_t afh[2][4], afl[2][4];
            #pragma unroll
            for (int mt = 0; mt < 2; ++mt) {
                int row = wm * 32 + mt * 16 + g;
                afh[mt][0] = *(const uint32_t*)&Ah[row    ][col    ];
                afh[mt][1] = *(const uint32_t*)&Ah[row + 8][col    ];
                afh[mt][2] = *(const uint32_t*)&Ah[row    ][col + 8];
                afh[mt][3] = *(const uint32_t*)&Ah[row + 8][col + 8];
                afl[mt][0] = *(const uint32_t*)&Al[row    ][col    ];
                afl[mt][1] = *(const uint32_t*)&Al[row + 8][col    ];
                afl[mt][2] = *(const uint32_t*)&Al[row    ][col + 8];
                afl[mt][3] = *(const uint32_t*)&Al[row + 8][col + 8];
            }
            uint32_t bfh[8][2], bfl[8][2];
            #pragma unroll
            for (int nt = 0; nt < 8; ++nt) {
                int rn = wn * 64 + nt * 8 + g;
                bfh[nt][0] = *(const uint32_t*)&Bh[rn][col    ];
                bfh[nt][1] = *(const uint32_t*)&Bh[rn][col + 8];
                bfl[nt][0] = *(const uint32_t*)&Bl[rn][col    ];
                bfl[nt][1] = *(const uint32_t*)&Bl[rn][col + 8];
            }
            #pragma unroll
            for (int mt = 0; mt < 2; ++mt)
                #pragma unroll
                for (int nt = 0; nt < 8; ++nt) {
                    MMA16816(acc[mt][nt], afh[mt], bfh[nt]);
                    MMA16816(acc[mt][nt], afh[mt], bfl[nt]);
                    MMA16816(acc[mt][nt], afl[mt], bfh[nt]);
                }
        }
        __syncthreads();
    }

    // epilogue: D layout c0:(g,2t) c1:(g,2t+1) c2:(g+8,2t) c3:(g+8,2t+1)
    #pragma unroll
    for (int mt = 0; mt < 2; ++mt) {
        int r0 = m0 + wm * 32 + mt * 16 + g;
        #pragma unroll
        for (int nt = 0; nt < 8; ++nt) {
            int cc = n0 + wn * 64 + nt * 8 + 2 * t;
            float b0 = __ldg(&bias[cc]);
            float b1 = __ldg(&bias[cc + 1]);
            *(float2*)&out[(size_t)r0 * Nstride + cc] =
                make_float2(acc[mt][nt][0] + b0, acc[mt][nt][1] + b1);
            *(float2*)&out[(size_t)(r0 + 8) * Nstride + cc] =
                make_float2(acc[mt][nt][2] + b0, acc[mt][nt][3] + b1);
        }
    }
}

// ============================================================================
// Fused window attention, register-tiled fp32.
// One CTA per window (256 threads), 4 heads serial.
// ============================================================================
__global__ void __launch_bounds__(256) attn_kernel(
    const float* __restrict__ qkv,        // [B*N, 384]
    const float* __restrict__ mask,       // [64, 49, 49]
    const float* __restrict__ rpb,        // [169, 4]
    const int*   __restrict__ relidx,     // [49, 49]
    float*       __restrict__ obuf)       // [B*N, 128]
{
    __shared__ float sm_mask[N_ * N_];                  // 2401
    __shared__ float sm_rpb[169 * NH_];                 // 676
    __shared__ __align__(16) float qT[32][60];          // [d][i], cols 49..51 zero pad
    __shared__ __align__(16) float kT[32][60];          // [d][j]
    __shared__ __align__(16) float sv[52][36];          // [j][d]
    __shared__ __align__(16) float sS[52 * 56];         // [i][j] stride 56

    const int b    = blockIdx.x;
    const int w    = b & (NW_ - 1);
    const int tid  = threadIdx.x;
    const int lane = tid & 31;
    const int warp = tid >> 5;

    for (int idx = tid; idx < N_ * N_; idx += 256)
        sm_mask[idx] = mask[w * (N_ * N_) + idx];
    for (int idx = tid; idx < 169 * NH_; idx += 256)
        sm_rpb[idx] = rpb[idx];
    if (tid < 96) {                        // zero the padding cols 49..51
        int d = tid / 3, c = 49 + tid % 3;
        qT[d][c] = 0.f; kT[d][c] = 0.f;
    }
    __syncthreads();

    for (int h = 0; h < NH_; ++h) {
        // ---- load q (transposed), k (transposed), v for this head ----
        for (int idx = tid; idx < N_ * 8; idx += 256) {   // 392 work items
            int i  = idx >> 3;
            int d0 = (idx & 7) * 4;
            const float* base = qkv + (size_t)(b * N_ + i) * QKV_N + h * HD_ + d0;
            float4 qv = *(const float4*)(base);
            float4 kv = *(const float4*)(base + 128);
            float4 vv = *(const float4*)(base + 256);
            qT[d0    ][i] = qv.x; qT[d0 + 1][i] = qv.y;
            qT[d0 + 2][i] = qv.z; qT[d0 + 3][i] = qv.w;
            kT[d0    ][i] = kv.x; kT[d0 + 1][i] = kv.y;
            kT[d0 + 2][i] = kv.z; kT[d0 + 3][i] = kv.w;
            *(float4*)&sv[i][d0] = vv;
        }
        __syncthreads();

        // ---- S = scale*q@k^T + rpb + mask   (4x4 tiles, 13x13 grid) ----
        if (tid < 169) {
            const int i0 = 4 * (tid % 13);
            const int j0 = 4 * (tid / 13);
            float a4[4][4];
            #pragma unroll
            for (int ii = 0; ii < 4; ++ii)
                #pragma unroll
                for (int jj = 0; jj < 4; ++jj) a4[ii][jj] = 0.f;
            #pragma unroll
            for (int d = 0; d < HD_; ++d) {
                float4 qa = *(const float4*)&qT[d][i0];
                float4 kb = *(const float4*)&kT[d][j0];
                float qr[4] = {qa.x, qa.y, qa.z, qa.w};
                float kr[4] = {kb.x, kb.y, kb.z, kb.w};
                #pragma unroll
                for (int ii = 0; ii < 4; ++ii)
                    #pragma unroll
                    for (int jj = 0; jj < 4; ++jj)
                        a4[ii][jj] += qr[ii] * kr[jj];
            }
            #pragma unroll
            for (int ii = 0; ii < 4; ++ii) {
                int i = i0 + ii;
                if (i < N_) {
                    #pragma unroll
                    for (int jj = 0; jj < 4; ++jj) {
                        int j = j0 + jj;
                        if (j < N_) {
                            int r = __ldg(&relidx[i * N_ + j]);
                            sS[i * 56 + j] = a4[ii][jj] * SCALE_
                                           + sm_rpb[r * NH_ + h]
                                           + sm_mask[i * N_ + j];
                        }
                    }
                }
            }
        }
        __syncthreads();

        // ---- softmax over rows (warp per row) ----
        for (int i = warp; i < N_; i += 8) {
            float* row = &sS[i * 56];
            float x0 = row[lane];
            float x1 = (lane + 32 < N_) ? row[lane + 32] : -1e30f;
            float m = fmaxf(x0, x1);
            #pragma unroll
            for (int off = 16; off > 0; off >>= 1)
                m = fmaxf(m, __shfl_xor_sync(0xffffffffu, m, off));
            float e0 = __expf(x0 - m);
            float e1 = (lane + 32 < N_) ? __expf(x1 - m) : 0.f;
            float s = e0 + e1;
            #pragma unroll
            for (int off = 16; off > 0; off >>= 1)
                s += __shfl_xor_sync(0xffffffffu, s, off);
            float inv = __frcp_rn(s);
            row[lane] = e0 * inv;
            if (lane + 32 < N_) row[lane + 32] = e1 * inv;
        }
        __syncthreads();

        // ---- O = S @ V   (2x4 tiles, 25x8 grid) ----
        if (tid < 200) {
            const int d0 = (tid & 7) * 4;
            const int i0 = (tid >> 3) * 2;
            float a0[4] = {0.f, 0.f, 0.f, 0.f};
            float a1[4] = {0.f, 0.f, 0.f, 0.f};
            const float* s0 = &sS[i0 * 56];
            const float* s1 = &sS[(i0 + 1) * 56];
            #pragma unroll
            for (int j = 0; j < N_; ++j) {
                float4 vv = *(const float4*)&sv[j][d0];
                float p0 = s0[j];
                float p1 = s1[j];
                a0[0] += p0 * vv.x; a0[1] += p0 * vv.y;
                a0[2] += p0 * vv.z; a0[3] += p0 * vv.w;
                a1[0] += p1 * vv.x; a1[1] += p1 * vv.y;
                a1[2] += p1 * vv.z; a1[3] += p1 * vv.w;
            }
            float* o0 = &obuf[(size_t)(b * N_ + i0) * DIM_ + h * HD_ + d0];
            *(float4*)o0 = make_float4(a0[0], a0[1], a0[2], a0[3]);
            if (i0 + 1 < N_) {
                float* o1 = o0 + DIM_;
                *(float4*)o1 = make_float4(a1[0], a1[1], a1[2], a1[3]);
            }
        }
        __syncthreads();   // protect smem before next head overwrites
    }
}

// ============================================================================
// launch
// ============================================================================
extern "C" void kernel_launch(void* const* d_in, const int* in_sizes, int n_in,
                              void* d_out, int out_size)
{
    const float* x      = (const float*)d_in[0];
    const float* mask   = (const float*)d_in[1];
    const float* qkv_w  = (const float*)d_in[2];
    const float* qkv_b  = (const float*)d_in[3];
    const float* proj_w = (const float*)d_in[4];
    const float* proj_b = (const float*)d_in[5];
    const float* rpb    = (const float*)d_in[6];
    const int*   rel    = (const int*)d_in[7];
    float* out = (float*)d_out;

    float* qkv_buf = nullptr;
    float* obuf = nullptr;
    cudaGetSymbolAddress((void**)&qkv_buf, g_qkv);
    cudaGetSymbolAddress((void**)&obuf, g_obuf);

    // QKV projection: [401408,128] @ [384,128]^T -> [401408,384]
    gemm_mma<<<dim3(QKV_N / 128, M_TOTAL / 128), 256>>>(x, qkv_w, qkv_b, qkv_buf, QKV_N);
    // windowed attention
    attn_kernel<<<B_, 256>>>(qkv_buf, mask, rpb, rel, obuf);
    // output projection: [401408,128] @ [128,128]^T -> [401408,128]
    gemm_mma<<<dim3(1, M_TOTAL / 128), 256>>>(obuf, proj_w, proj_b, out, DIM_);
}

// round 4
// speedup vs baseline: 2.2544x; 1.1408x over previous
#include <cuda_runtime.h>
#include <cuda_bf16.h>
#include <math.h>
#include <stdint.h>

// ---------------- problem constants ----------------
#define B_      8192
#define N_      49
#define DIM_    128
#define NH_     4
#define HD_     32
#define NW_     64
#define QKV_N   384
#define M_TOTAL (B_ * N_)          // 401408
#define SCALE_  0.17677669529663687f  // 32^-0.5

// ---------------- scratch ----------------
__device__ float g_qkv[(size_t)M_TOTAL * QKV_N];   // [B*N, 384]
__device__ float g_obuf[(size_t)M_TOTAL * DIM_];   // [B*N, 128]

#define MMA16816(d, a, b)                                                     \
  asm volatile(                                                               \
      "mma.sync.aligned.m16n8k16.row.col.f32.bf16.bf16.f32 "                  \
      "{%0,%1,%2,%3}, {%4,%5,%6,%7}, {%8,%9}, {%0,%1,%2,%3};"                 \
      : "+f"(d[0]), "+f"(d[1]), "+f"(d[2]), "+f"(d[3])                        \
      : "r"(a[0]), "r"(a[1]), "r"(a[2]), "r"(a[3]), "r"(b[0]), "r"(b[1]))

__device__ __forceinline__ void cvt_store4(__nv_bfloat16* ph, __nv_bfloat16* pl, float4 v)
{
    float f[4] = {v.x, v.y, v.z, v.w};
    __nv_bfloat16 h[4], l[4];
    #pragma unroll
    for (int i = 0; i < 4; ++i) {
        h[i] = __float2bfloat16(f[i]);
        l[i] = __float2bfloat16(f[i] - __bfloat162float(h[i]));
    }
    *(__nv_bfloat162*)(ph)     = __halves2bfloat162(h[0], h[1]);
    *(__nv_bfloat162*)(ph + 2) = __halves2bfloat162(h[2], h[3]);
    *(__nv_bfloat162*)(pl)     = __halves2bfloat162(l[0], l[1]);
    *(__nv_bfloat162*)(pl + 2) = __halves2bfloat162(l[2], l[3]);
}

// ============================================================================
// Split-bf16 tensor-core GEMM (unchanged from round 3; passes at 1e-5).
// ============================================================================
__global__ void __launch_bounds__(256) gemm_mma(
    const float* __restrict__ X, const float* __restrict__ W,
    const float* __restrict__ bias, float* __restrict__ out, int Nstride)
{
    __shared__ __align__(16) __nv_bfloat16 Ah[128][40], Al[128][40];
    __shared__ __align__(16) __nv_bfloat16 Bh[128][40], Bl[128][40];

    const int tid  = threadIdx.x;
    const int lane = tid & 31;
    const int warp = tid >> 5;
    const int wm   = warp & 3;
    const int wn   = warp >> 2;
    const int g    = lane >> 2;
    const int t    = lane & 3;

    const int m0 = blockIdx.y * 128;
    const int n0 = blockIdx.x * 128;

    float acc[2][8][4];
    #pragma unroll
    for (int mt = 0; mt < 2; ++mt)
        #pragma unroll
        for (int nt = 0; nt < 8; ++nt)
            #pragma unroll
            for (int r = 0; r < 4; ++r) acc[mt][nt][r] = 0.f;

    for (int kc = 0; kc < 128; kc += 32) {
        #pragma unroll
        for (int r = 0; r < 4; ++r) {
            int idx = tid + r * 256;
            int row = idx >> 3;
            int c4  = (idx & 7) * 4;
            float4 xv = *(const float4*)&X[(size_t)(m0 + row) * 128 + kc + c4];
            cvt_store4(&Ah[row][c4], &Al[row][c4], xv);
            float4 wv = *(const float4*)&W[(size_t)(n0 + row) * 128 + kc + c4];
            cvt_store4(&Bh[row][c4], &Bl[row][c4], wv);
        }
        __syncthreads();

        #pragma unroll
        for (int ks = 0; ks < 2; ++ks) {
            const int col = ks * 16 + 2 * t;
            uint32_t afh[2][4], afl[2][4];
            #pragma unroll
            for (int mt = 0; mt < 2; ++mt) {
                int row = wm * 32 + mt * 16 + g;
                afh[mt][0] = *(const uint32_t*)&Ah[row    ][col    ];
                afh[mt][1] = *(const uint32_t*)&Ah[row + 8][col    ];
                afh[mt][2] = *(const uint32_t*)&Ah[row    ][col + 8];
                afh[mt][3] = *(const uint32_t*)&Ah[row + 8][col + 8];
                afl[mt][0] = *(const uint32_t*)&Al[row    ][col    ];
                afl[mt][1] = *(const uint32_t*)&Al[row + 8][col    ];
                afl[mt][2] = *(const uint32_t*)&Al[row    ][col + 8];
                afl[mt][3] = *(const uint32_t*)&Al[row + 8][col + 8];
            }
            uint32_t bfh[8][2], bfl[8][2];
            #pragma unroll
            for (int nt = 0; nt < 8; ++nt) {
                int rn = wn * 64 + nt * 8 + g;
                bfh[nt][0] = *(const uint32_t*)&Bh[rn][col    ];
                bfh[nt][1] = *(const uint32_t*)&Bh[rn][col + 8];
                bfl[nt][0] = *(const uint32_t*)&Bl[rn][col    ];
                bfl[nt][1] = *(const uint32_t*)&Bl[rn][col + 8];
            }
            #pragma unroll
            for (int mt = 0; mt < 2; ++mt)
                #pragma unroll
                for (int nt = 0; nt < 8; ++nt) {
                    MMA16816(acc[mt][nt], afh[mt], bfh[nt]);
                    MMA16816(acc[mt][nt], afh[mt], bfl[nt]);
                    MMA16816(acc[mt][nt], afl[mt], bfh[nt]);
                }
        }
        __syncthreads();
    }

    #pragma unroll
    for (int mt = 0; mt < 2; ++mt) {
        int r0 = m0 + wm * 32 + mt * 16 + g;
        #pragma unroll
        for (int nt = 0; nt < 8; ++nt) {
            int cc = n0 + wn * 64 + nt * 8 + 2 * t;
            float b0 = __ldg(&bias[cc]);
            float b1 = __ldg(&bias[cc + 1]);
            *(float2*)&out[(size_t)r0 * Nstride + cc] =
                make_float2(acc[mt][nt][0] + b0, acc[mt][nt][1] + b1);
            *(float2*)&out[(size_t)(r0 + 8) * Nstride + cc] =
                make_float2(acc[mt][nt][2] + b0, acc[mt][nt][3] + b1);
        }
    }
}

// ============================================================================
// MMA window attention. One CTA / window, 256 threads, 4 heads serial.
// QK^T and P@V both split-bf16 m16n8k16 (3-pass). N padded 49->64.
// ============================================================================
struct AttnSmem {
    __nv_bfloat16 qh[64][40], ql[64][40];   // [i][d] A-operand, 80B rows
    __nv_bfloat16 kh[64][40], kl[64][40];   // [j][d] B-operand
    __nv_bfloat16 vTh[32][72], vTl[32][72]; // [d][j] B-operand for PV, 144B rows
    __nv_bfloat16 ph[64][72], pl[64][72];   // [i][j] A-operand for PV
    float mask[N_ * N_];                    // 9604B
    float rpb[169 * NH_];                   // 2704B
    float sS[49][68];                       // logits, 272B rows
};
#define ATTN_SMEM_BYTES sizeof(AttnSmem)
#define BF16_ZERO_BYTES (sizeof(__nv_bfloat16) * (4*64*40 + 2*32*72 + 2*64*72))  // 48128

__global__ void __launch_bounds__(256) attn_mma(
    const float* __restrict__ qkv,        // [B*N, 384]
    const float* __restrict__ maskg,      // [64, 49, 49]
    const float* __restrict__ rpbg,       // [169, 4]
    const int*   __restrict__ relidx,     // [49, 49]
    float*       __restrict__ obuf)       // [B*N, 128]
{
    extern __shared__ __align__(16) char smem_raw[];
    AttnSmem* s = (AttnSmem*)smem_raw;

    const int b    = blockIdx.x;
    const int w    = b & (NW_ - 1);
    const int tid  = threadIdx.x;
    const int lane = tid & 31;
    const int warp = tid >> 5;
    const int g    = lane >> 2;      // 0..7
    const int t    = lane & 3;       // 0..3
    const int wm   = warp & 3;       // m-tile (16 rows)
    const int wn   = warp >> 2;      // 0..1

    // one-time zero of all bf16 operand arrays (padding must be 0)
    {
        uint4 zz = make_uint4(0, 0, 0, 0);
        uint4* zp = (uint4*)smem_raw;
        for (int i = tid; i < (int)(BF16_ZERO_BYTES / 16); i += 256) zp[i] = zz;
    }
    for (int i = tid; i < N_ * N_; i += 256) s->mask[i] = maskg[w * N_ * N_ + i];
    for (int i = tid; i < 169 * NH_; i += 256) s->rpb[i] = rpbg[i];
    __syncthreads();

    for (int h = 0; h < NH_; ++h) {
        // ---- convert q,k (hi/lo, [i][d]) and v (hi/lo, transposed [d][j]) ----
        for (int idx = tid; idx < N_ * 8; idx += 256) {
            int i  = idx >> 3;
            int d0 = (idx & 7) * 4;
            const float* base = qkv + (size_t)(b * N_ + i) * QKV_N + h * HD_ + d0;
            float4 qv = *(const float4*)(base);
            float4 kv = *(const float4*)(base + 128);
            float4 vv = *(const float4*)(base + 256);
            cvt_store4(&s->qh[i][d0], &s->ql[i][d0], qv);
            cvt_store4(&s->kh[i][d0], &s->kl[i][d0], kv);
            float vf[4] = {vv.x, vv.y, vv.z, vv.w};
            #pragma unroll
            for (int r = 0; r < 4; ++r) {
                __nv_bfloat16 hi = __float2bfloat16(vf[r]);
                __nv_bfloat16 lo = __float2bfloat16(vf[r] - __bfloat162float(hi));
                s->vTh[d0 + r][i] = hi;
                s->vTl[d0 + r][i] = lo;
            }
        }
        __syncthreads();

        // ---- S = Q K^T (warp: rows 16wm..+15, cols 32wn..+31 = 4 n-tiles) ----
        {
            float acc[4][4];
            #pragma unroll
            for (int nt = 0; nt < 4; ++nt)
                #pragma unroll
                for (int r = 0; r < 4; ++r) acc[nt][r] = 0.f;

            #pragma unroll
            for (int ks = 0; ks < 2; ++ks) {
                const int col = ks * 16 + 2 * t;
                const int row = 16 * wm + g;
                uint32_t ah[4], al[4];
                ah[0] = *(const uint32_t*)&s->qh[row    ][col    ];
                ah[1] = *(const uint32_t*)&s->qh[row + 8][col    ];
                ah[2] = *(const uint32_t*)&s->qh[row    ][col + 8];
                ah[3] = *(const uint32_t*)&s->qh[row + 8][col + 8];
                al[0] = *(const uint32_t*)&s->ql[row    ][col    ];
                al[1] = *(const uint32_t*)&s->ql[row + 8][col    ];
                al[2] = *(const uint32_t*)&s->ql[row    ][col + 8];
                al[3] = *(const uint32_t*)&s->ql[row + 8][col + 8];
                #pragma unroll
                for (int nt = 0; nt < 4; ++nt) {
                    int rn = 32 * wn + 8 * nt + g;
                    uint32_t bh[2], bl[2];
                    bh[0] = *(const uint32_t*)&s->kh[rn][col    ];
                    bh[1] = *(const uint32_t*)&s->kh[rn][col + 8];
                    bl[0] = *(const uint32_t*)&s->kl[rn][col    ];
                    bl[1] = *(const uint32_t*)&s->kl[rn][col + 8];
                    MMA16816(acc[nt], ah, bh);
                    MMA16816(acc[nt], ah, bl);
                    MMA16816(acc[nt], al, bh);
                }
            }
            // epilogue: scale + rpb + mask, write valid region only
            #pragma unroll
            for (int nt = 0; nt < 4; ++nt) {
                int c = 32 * wn + 8 * nt + 2 * t;
                #pragma unroll
                for (int half = 0; half < 2; ++half) {
                    int r = 16 * wm + g + 8 * half;
                    if (r < N_) {
                        if (c < N_) {
                            int ri = __ldg(&relidx[r * N_ + c]);
                            s->sS[r][c] = acc[nt][2 * half] * SCALE_
                                        + s->rpb[ri * NH_ + h] + s->mask[r * N_ + c];
                        }
                        if (c + 1 < N_) {
                            int ri = __ldg(&relidx[r * N_ + c + 1]);
                            s->sS[r][c + 1] = acc[nt][2 * half + 1] * SCALE_
                                            + s->rpb[ri * NH_ + h] + s->mask[r * N_ + c + 1];
                        }
                    }
                }
            }
        }
        __syncthreads();

        // ---- softmax rows, emit P as hi/lo bf16 ----
        for (int i = warp; i < N_; i += 8) {
            const float* row = s->sS[i];
            float x0 = row[lane];
            float x1 = (lane + 32 < N_) ? row[lane + 32] : -1e30f;
            float m = fmaxf(x0, x1);
            #pragma unroll
            for (int off = 16; off > 0; off >>= 1)
                m = fmaxf(m, __shfl_xor_sync(0xffffffffu, m, off));
            float e0 = __expf(x0 - m);
            float e1 = (lane + 32 < N_) ? __expf(x1 - m) : 0.f;
            float sum = e0 + e1;
            #pragma unroll
            for (int off = 16; off > 0; off >>= 1)
                sum += __shfl_xor_sync(0xffffffffu, sum, off);
            float inv = __frcp_rn(sum);
            float p0 = e0 * inv;
            __nv_bfloat16 h0 = __float2bfloat16(p0);
            s->ph[i][lane] = h0;
            s->pl[i][lane] = __float2bfloat16(p0 - __bfloat162float(h0));
            if (lane + 32 < N_) {
                float p1 = e1 * inv;
                __nv_bfloat16 h1 = __float2bfloat16(p1);
                s->ph[i][lane + 32] = h1;
                s->pl[i][lane + 32] = __float2bfloat16(p1 - __bfloat162float(h1));
            }
        }
        __syncthreads();

        // ---- O = P V (warp: rows 16wm..+15, d-cols 16wn..+15 = 2 n-tiles) ----
        {
            float oacc[2][4];
            #pragma unroll
            for (int nt = 0; nt < 2; ++nt)
                #pragma unroll
                for (int r = 0; r < 4; ++r) oacc[nt][r] = 0.f;

            #pragma unroll
            for (int ks = 0; ks < 4; ++ks) {
                const int col = ks * 16 + 2 * t;   // j
                const int row = 16 * wm + g;
                uint32_t ah[4], al[4];
                ah[0] = *(const uint32_t*)&s->ph[row    ][col    ];
                ah[1] = *(const uint32_t*)&s->ph[row + 8][col    ];
                ah[2] = *(const uint32_t*)&s->ph[row    ][col + 8];
                ah[3] = *(const uint32_t*)&s->ph[row + 8][col + 8];
                al[0] = *(const uint32_t*)&s->pl[row    ][col    ];
                al[1] = *(const uint32_t*)&s->pl[row + 8][col    ];
                al[2] = *(const uint32_t*)&s->pl[row    ][col + 8];
                al[3] = *(const uint32_t*)&s->pl[row + 8][col + 8];
                #pragma unroll
                for (int nt = 0; nt < 2; ++nt) {
                    int rn = 16 * wn + 8 * nt + g;   // d
                    uint32_t bh[2], bl[2];
                    bh[0] = *(const uint32_t*)&s->vTh[rn][col    ];
                    bh[1] = *(const uint32_t*)&s->vTh[rn][col + 8];
                    bl[0] = *(const uint32_t*)&s->vTl[rn][col    ];
                    bl[1] = *(const uint32_t*)&s->vTl[rn][col + 8];
                    MMA16816(oacc[nt], ah, bh);
                    MMA16816(oacc[nt], ah, bl);
                    MMA16816(oacc[nt], al, bh);
                }
            }
            #pragma unroll
            for (int nt = 0; nt < 2; ++nt) {
                int c = 16 * wn + 8 * nt + 2 * t;       // 0..31
                int r = 16 * wm + g;
                if (r < N_)
                    *(float2*)&obuf[(size_t)(b * N_ + r) * DIM_ + h * HD_ + c] =
                        make_float2(oacc[nt][0], oacc[nt][1]);
                if (r + 8 < N_)
                    *(float2*)&obuf[(size_t)(b * N_ + r + 8) * DIM_ + h * HD_ + c] =
                        make_float2(oacc[nt][2], oacc[nt][3]);
            }
        }
        __syncthreads();   // protect operand smem before next head
    }
}

// ============================================================================
// launch
// ============================================================================
extern "C" void kernel_launch(void* const* d_in, const int* in_sizes, int n_in,
                              void* d_out, int out_size)
{
    const float* x      = (const float*)d_in[0];
    const float* mask   = (const float*)d_in[1];
    const float* qkv_w  = (const float*)d_in[2];
    const float* qkv_b  = (const float*)d_in[3];
    const float* proj_w = (const float*)d_in[4];
    const float* proj_b = (const float*)d_in[5];
    const float* rpb    = (const float*)d_in[6];
    const int*   rel    = (const int*)d_in[7];
    float* out = (float*)d_out;

    float* qkv_buf = nullptr;
    float* obuf = nullptr;
    cudaGetSymbolAddress((void**)&qkv_buf, g_qkv);
    cudaGetSymbolAddress((void**)&obuf, g_obuf);

    static bool attr_set = false;
    if (!attr_set) {
        cudaFuncSetAttribute(attn_mma, cudaFuncAttributeMaxDynamicSharedMemorySize,
                             (int)ATTN_SMEM_BYTES);
        attr_set = true;
    }

    gemm_mma<<<dim3(QKV_N / 128, M_TOTAL / 128), 256>>>(x, qkv_w, qkv_b, qkv_buf, QKV_N);
    attn_mma<<<B_, 256, ATTN_SMEM_BYTES>>>(qkv_buf, mask, rpb, rel, obuf);
    gemm_mma<<<dim3(1, M_TOTAL / 128), 256>>>(obuf, proj_w, proj_b, out, DIM_);
}

// round 5
// speedup vs baseline: 2.6665x; 1.1828x over previous
#include <cuda_runtime.h>
#include <cuda_bf16.h>
#include <math.h>
#include <stdint.h>

// ---------------- problem constants ----------------
#define B_      8192
#define N_      49
#define DIM_    128
#define NH_     4
#define HD_     32
#define NW_     64
#define QKV_N   384
#define M_TOTAL (B_ * N_)          // 401408
#define SCALE_  0.17677669529663687f  // 32^-0.5

// ---------------- scratch (device globals; allocation-free) ----------------
__device__ __nv_bfloat16 g_xh[(size_t)M_TOTAL * DIM_];     // x hi
__device__ __nv_bfloat16 g_xl[(size_t)M_TOTAL * DIM_];     // x lo
__device__ __nv_bfloat16 g_qkvh[(size_t)M_TOTAL * QKV_N];  // qkv hi
__device__ __nv_bfloat16 g_qkvl[(size_t)M_TOTAL * QKV_N];  // qkv lo
__device__ __nv_bfloat16 g_oh[(size_t)M_TOTAL * DIM_];     // attn out hi
__device__ __nv_bfloat16 g_ol[(size_t)M_TOTAL * DIM_];     // attn out lo
__device__ __nv_bfloat16 g_wqh[QKV_N * DIM_], g_wql[QKV_N * DIM_];
__device__ __nv_bfloat16 g_wph[DIM_ * DIM_], g_wpl[DIM_ * DIM_];
__device__ float g_rmb[NW_ * NH_ * N_ * N_];               // mask + rpb fused

// ---------------- helpers ----------------
#define MMA16816(d, a, b)                                                     \
  asm volatile(                                                               \
      "mma.sync.aligned.m16n8k16.row.col.f32.bf16.bf16.f32 "                  \
      "{%0,%1,%2,%3}, {%4,%5,%6,%7}, {%8,%9}, {%0,%1,%2,%3};"                 \
      : "+f"(d[0]), "+f"(d[1]), "+f"(d[2]), "+f"(d[3])                        \
      : "r"(a[0]), "r"(a[1]), "r"(a[2]), "r"(a[3]), "r"(b[0]), "r"(b[1]))

#define CP_ASYNC_COMMIT asm volatile("cp.async.commit_group;" ::: "memory")
#define CP_ASYNC_WAIT_1 asm volatile("cp.async.wait_group 1;" ::: "memory")
#define CP_ASYNC_WAIT_0 asm volatile("cp.async.wait_group 0;" ::: "memory")

__device__ __forceinline__ void cp16(void* smem, const void* gmem)
{
    uint32_t s = (uint32_t)__cvta_generic_to_shared(smem);
    asm volatile("cp.async.cg.shared.global [%0], [%1], 16;" :: "r"(s), "l"(gmem));
}

// pack two floats into bf16x2 hi + bf16x2 lo words
__device__ __forceinline__ void pack_hl(float a, float b, uint32_t& hp, uint32_t& lp)
{
    __nv_bfloat16 ah = __float2bfloat16(a), bh = __float2bfloat16(b);
    __nv_bfloat16 al = __float2bfloat16(a - __bfloat162float(ah));
    __nv_bfloat16 bl = __float2bfloat16(b - __bfloat162float(bh));
    __nv_bfloat162 hv = __halves2bfloat162(ah, bh);
    __nv_bfloat162 lv = __halves2bfloat162(al, bl);
    hp = *(uint32_t*)&hv;
    lp = *(uint32_t*)&lv;
}

// ============================================================================
// setup kernels
// ============================================================================
__global__ void convert_x(const float* __restrict__ x)
{
    size_t i = (size_t)blockIdx.x * 256 + threadIdx.x;   // float4 index, exact grid
    float4 v = ((const float4*)x)[i];
    uint32_t h0, l0, h1, l1;
    pack_hl(v.x, v.y, h0, l0);
    pack_hl(v.z, v.w, h1, l1);
    ((uint2*)g_xh)[i] = make_uint2(h0, h1);
    ((uint2*)g_xl)[i] = make_uint2(l0, l1);
}

__global__ void convert_w(const float* __restrict__ qkv_w, const float* __restrict__ proj_w)
{
    int i = blockIdx.x * 256 + threadIdx.x;  // float4 idx, 0..16383
    float4 v;
    if (i < 12288) v = ((const float4*)qkv_w)[i];
    else           v = ((const float4*)proj_w)[i - 12288];
    uint32_t h0, l0, h1, l1;
    pack_hl(v.x, v.y, h0, l0);
    pack_hl(v.z, v.w, h1, l1);
    if (i < 12288) {
        ((uint2*)g_wqh)[i] = make_uint2(h0, h1);
        ((uint2*)g_wql)[i] = make_uint2(l0, l1);
    } else {
        ((uint2*)g_wph)[i - 12288] = make_uint2(h0, h1);
        ((uint2*)g_wpl)[i - 12288] = make_uint2(l0, l1);
    }
}

__global__ void build_rmb(const float* __restrict__ mask, const float* __restrict__ rpb,
                          const int* __restrict__ rel)
{
    int t = blockIdx.x * 256 + threadIdx.x;   // 2401*256 grid = 614656 exact
    int ij = t % (N_ * N_);
    int wh = t / (N_ * N_);
    int h = wh & 3, w = wh >> 2;
    g_rmb[t] = mask[w * N_ * N_ + ij] + rpb[rel[ij] * NH_ + h];
}

// ============================================================================
// Pure-bf16 tensor-core GEMM: out = A @ B^T + bias.
// A = (Ahg, Alg) [M][128] hi/lo bf16; B = (Bhg, Blg) [N][128].
// 3-pass split: D += Ah*Bh + Ah*Bl + Al*Bh.
// CTA 128x128, k-chunk 32, 2-stage cp.async pipeline, 256 thr, 2 CTA/SM.
// OUT_BF16: emit bf16 hi/lo; else fp32.
// ============================================================================
template<bool OUT_BF16>
__global__ void __launch_bounds__(256) gemm_bf16(
    const __nv_bfloat16* __restrict__ Ahg, const __nv_bfloat16* __restrict__ Alg,
    const __nv_bfloat16* __restrict__ Bhg, const __nv_bfloat16* __restrict__ Blg,
    const float* __restrict__ bias,
    float* __restrict__ outf, __nv_bfloat16* __restrict__ outh,
    __nv_bfloat16* __restrict__ outl, int Nstride)
{
    extern __shared__ __align__(16) __nv_bfloat16 sm[];
    const int STG = 128 * 40;                 // one stage slab (elems)
    __nv_bfloat16* sAh = sm;                  // [2][128][40]
    __nv_bfloat16* sAl = sm + 2 * STG;
    __nv_bfloat16* sBh = sm + 4 * STG;
    __nv_bfloat16* sBl = sm + 6 * STG;

    const int tid  = threadIdx.x;
    const int lane = tid & 31;
    const int warp = tid >> 5;
    const int wm   = warp & 3;
    const int wn   = warp >> 2;
    const int g    = lane >> 2;
    const int t    = lane & 3;

    const int m0 = blockIdx.y * 128;
    const int n0 = blockIdx.x * 128;

    float acc[2][8][4];
    #pragma unroll
    for (int mt = 0; mt < 2; ++mt)
        #pragma unroll
        for (int nt = 0; nt < 8; ++nt)
            #pragma unroll
            for (int r = 0; r < 4; ++r) acc[mt][nt][r] = 0.f;

    // ---- loader: 8 cp.async of 16B per thread per chunk ----
    auto load_stage = [&](int st, int kc) {
        #pragma unroll
        for (int it = 0; it < 2; ++it) {
            int idx = tid + it * 256;            // 0..511
            int row = idx >> 2;                  // 0..127
            int c8  = (idx & 3) * 8;             // 0,8,16,24
            size_t gA = (size_t)(m0 + row) * DIM_ + kc + c8;
            size_t gB = (size_t)(n0 + row) * DIM_ + kc + c8;
            int so = st * STG + row * 40 + c8;
            cp16(sAh + so, Ahg + gA);
            cp16(sAl + so, Alg + gA);
            cp16(sBh + so, Bhg + gB);
            cp16(sBl + so, Blg + gB);
        }
    };

    load_stage(0, 0);  CP_ASYNC_COMMIT;
    load_stage(1, 32); CP_ASYNC_COMMIT;

    for (int c = 0; c < 4; ++c) {
        if (c < 3) { CP_ASYNC_WAIT_1; } else { CP_ASYNC_WAIT_0; }
        __syncthreads();

        const int st = c & 1;
        #pragma unroll
        for (int ks = 0; ks < 2; ++ks) {
            const int col = ks * 16 + 2 * t;
            uint32_t afh[2][4], afl[2][4];
            #pragma unroll
            for (int mt = 0; mt < 2; ++mt) {
                int row = wm * 32 + mt * 16 + g;
                int o0 = st * STG + row * 40 + col;
                afh[mt][0] = *(const uint32_t*)(sAh + o0);
                afh[mt][1] = *(const uint32_t*)(sAh + o0 + 8 * 40);
                afh[mt][2] = *(const uint32_t*)(sAh + o0 + 8);
                afh[mt][3] = *(const uint32_t*)(sAh + o0 + 8 * 40 + 8);
                afl[mt][0] = *(const uint32_t*)(sAl + o0);
                afl[mt][1] = *(const uint32_t*)(sAl + o0 + 8 * 40);
                afl[mt][2] = *(const uint32_t*)(sAl + o0 + 8);
                afl[mt][3] = *(const uint32_t*)(sAl + o0 + 8 * 40 + 8);
            }
            #pragma unroll
            for (int nt = 0; nt < 8; ++nt) {
                int rn = wn * 64 + nt * 8 + g;
                int ob = st * STG + rn * 40 + col;
                uint32_t bh[2], bl[2];
                bh[0] = *(const uint32_t*)(sBh + ob);
                bh[1] = *(const uint32_t*)(sBh + ob + 8);
                bl[0] = *(const uint32_t*)(sBl + ob);
                bl[1] = *(const uint32_t*)(sBl + ob + 8);
                #pragma unroll
                for (int mt = 0; mt < 2; ++mt) {
                    MMA16816(acc[mt][nt], afh[mt], bh);
                    MMA16816(acc[mt][nt], afh[mt], bl);
                    MMA16816(acc[mt][nt], afl[mt], bh);
                }
            }
        }
        __syncthreads();
        if (c < 2) { load_stage(st, (c + 2) * 32); CP_ASYNC_COMMIT; }
    }

    // ---- epilogue ----
    #pragma unroll
    for (int mt = 0; mt < 2; ++mt) {
        int r0 = m0 + wm * 32 + mt * 16 + g;
        #pragma unroll
        for (int nt = 0; nt < 8; ++nt) {
            int cc = n0 + wn * 64 + nt * 8 + 2 * t;
            float b0 = __ldg(&bias[cc]);
            float b1 = __ldg(&bias[cc + 1]);
            float v00 = acc[mt][nt][0] + b0, v01 = acc[mt][nt][1] + b1;
            float v10 = acc[mt][nt][2] + b0, v11 = acc[mt][nt][3] + b1;
            if (OUT_BF16) {
                uint32_t hp, lp;
                pack_hl(v00, v01, hp, lp);
                *(uint32_t*)&outh[(size_t)r0 * Nstride + cc] = hp;
                *(uint32_t*)&outl[(size_t)r0 * Nstride + cc] = lp;
                pack_hl(v10, v11, hp, lp);
                *(uint32_t*)&outh[(size_t)(r0 + 8) * Nstride + cc] = hp;
                *(uint32_t*)&outl[(size_t)(r0 + 8) * Nstride + cc] = lp;
            } else {
                *(float2*)&outf[(size_t)r0 * Nstride + cc] = make_float2(v00, v01);
                *(float2*)&outf[(size_t)(r0 + 8) * Nstride + cc] = make_float2(v10, v11);
            }
        }
    }
}

// ============================================================================
// Register-resident MMA window attention.
// One CTA/window, 512 threads (16 warps). warp -> (head = w>>2, mtile = w&3).
// Single __syncthreads(); P stays in registers (C-frag == A-frag layout).
// ============================================================================
#define QROW 136            // q/k smem row stride (bf16)
#define VROW 72             // vT smem row stride
#define ASM_Q (64 * QROW)   // one q/k array
#define ASM_V (128 * VROW)
#define ATTN_SM_ELEMS (4 * ASM_Q + 2 * ASM_V)   // 53248 bf16 = 106496 B

__global__ void __launch_bounds__(512) attn_mma(
    const __nv_bfloat16* __restrict__ qkvh, const __nv_bfloat16* __restrict__ qkvl,
    const float* __restrict__ rmb,
    __nv_bfloat16* __restrict__ oh, __nv_bfloat16* __restrict__ ol)
{
    extern __shared__ __align__(16) __nv_bfloat16 sm[];
    __nv_bfloat16* sqh = sm;
    __nv_bfloat16* sql = sm + ASM_Q;
    __nv_bfloat16* skh = sm + 2 * ASM_Q;
    __nv_bfloat16* skl = sm + 3 * ASM_Q;
    __nv_bfloat16* svh = sm + 4 * ASM_Q;
    __nv_bfloat16* svl = sm + 4 * ASM_Q + ASM_V;

    const int b    = blockIdx.x;
    const int tid  = threadIdx.x;
    const int lane = tid & 31;
    const int warp = tid >> 5;
    const int g    = lane >> 2;
    const int t    = lane & 3;
    const int h    = warp >> 2;
    const int wm   = warp & 3;

    // zero all operand smem (pad rows/cols must be 0, never NaN)
    {
        uint4 zz = make_uint4(0, 0, 0, 0);
        uint4* zp = (uint4*)sm;
        #pragma unroll 4
        for (int i = tid; i < ATTN_SM_ELEMS / 8; i += 512) zp[i] = zz;
    }
    __syncthreads();

    // ---- load q,k (row copies via cp.async) ----
    for (int idx = tid; idx < 49 * 16; idx += 512) {
        int i = idx >> 4, seg = (idx & 15) * 8;
        size_t gb = (size_t)(b * N_ + i) * QKV_N + seg;
        cp16(sqh + i * QROW + seg, qkvh + gb);
        cp16(sql + i * QROW + seg, qkvl + gb);
        cp16(skh + i * QROW + seg, qkvh + gb + 128);
        cp16(skl + i * QROW + seg, qkvl + gb + 128);
    }
    // ---- load v transposed: [d][j] ----
    for (int idx = tid; idx < 49 * 64; idx += 512) {
        int dp = idx & 63, i = idx >> 6;
        size_t gb = (size_t)(b * N_ + i) * QKV_N + 256 + 2 * dp;
        uint32_t vh = *(const uint32_t*)(qkvh + gb);
        uint32_t vl = *(const uint32_t*)(qkvl + gb);
        int d0 = 2 * dp;
        ((uint16_t*)svh)[d0 * VROW + i]       = (uint16_t)(vh & 0xffff);
        ((uint16_t*)svh)[(d0 + 1) * VROW + i] = (uint16_t)(vh >> 16);
        ((uint16_t*)svl)[d0 * VROW + i]       = (uint16_t)(vl & 0xffff);
        ((uint16_t*)svl)[(d0 + 1) * VROW + i] = (uint16_t)(vl >> 16);
    }
    CP_ASYNC_COMMIT; CP_ASYNC_WAIT_0;
    __syncthreads();

    const int hoff = h * HD_;
    const int r0 = 16 * wm + g;
    const int r1 = r0 + 8;

    // ---- S = Q K^T (16 rows x 64 cols per warp) ----
    float sacc[8][4];
    #pragma unroll
    for (int nt = 0; nt < 8; ++nt)
        #pragma unroll
        for (int r = 0; r < 4; ++r) sacc[nt][r] = 0.f;

    #pragma unroll
    for (int ks = 0; ks < 2; ++ks) {
        const int col = hoff + ks * 16 + 2 * t;
        uint32_t ah[4], al[4];
        int oa = r0 * QROW + col;
        ah[0] = *(const uint32_t*)(sqh + oa);
        ah[1] = *(const uint32_t*)(sqh + oa + 8 * QROW);
        ah[2] = *(const uint32_t*)(sqh + oa + 8);
        ah[3] = *(const uint32_t*)(sqh + oa + 8 * QROW + 8);
        al[0] = *(const uint32_t*)(sql + oa);
        al[1] = *(const uint32_t*)(sql + oa + 8 * QROW);
        al[2] = *(const uint32_t*)(sql + oa + 8);
        al[3] = *(const uint32_t*)(sql + oa + 8 * QROW + 8);
        #pragma unroll
        for (int nt = 0; nt < 8; ++nt) {
            int ob = (8 * nt + g) * QROW + col;
            uint32_t bh[2], bl[2];
            bh[0] = *(const uint32_t*)(skh + ob);
            bh[1] = *(const uint32_t*)(skh + ob + 8);
            bl[0] = *(const uint32_t*)(skl + ob);
            bl[1] = *(const uint32_t*)(skl + ob + 8);
            MMA16816(sacc[nt], ah, bh);
            MMA16816(sacc[nt], ah, bl);
            MMA16816(sacc[nt], al, bh);
        }
    }

    // ---- bias + mask, register softmax (quad shuffles) ----
    const float* rmbw = rmb + (((b & (NW_ - 1)) * NH_ + h) * N_ * N_);
    float p0[16], p1[16];
    #pragma unroll
    for (int nt = 0; nt < 8; ++nt) {
        int c0 = 8 * nt + 2 * t;
        int c1 = c0 + 1;
        p0[2 * nt]     = (r0 < N_ && c0 < N_) ? fmaf(sacc[nt][0], SCALE_, __ldg(rmbw + r0 * N_ + c0)) : -1e30f;
        p0[2 * nt + 1] = (r0 < N_ && c1 < N_) ? fmaf(sacc[nt][1], SCALE_, __ldg(rmbw + r0 * N_ + c1)) : -1e30f;
        p1[2 * nt]     = (r1 < N_ && c0 < N_) ? fmaf(sacc[nt][2], SCALE_, __ldg(rmbw + r1 * N_ + c0)) : -1e30f;
        p1[2 * nt + 1] = (r1 < N_ && c1 < N_) ? fmaf(sacc[nt][3], SCALE_, __ldg(rmbw + r1 * N_ + c1)) : -1e30f;
    }
    float m0 = -1e30f, m1 = -1e30f;
    #pragma unroll
    for (int i = 0; i < 16; ++i) { m0 = fmaxf(m0, p0[i]); m1 = fmaxf(m1, p1[i]); }
    m0 = fmaxf(m0, __shfl_xor_sync(0xffffffffu, m0, 1));
    m0 = fmaxf(m0, __shfl_xor_sync(0xffffffffu, m0, 2));
    m1 = fmaxf(m1, __shfl_xor_sync(0xffffffffu, m1, 1));
    m1 = fmaxf(m1, __shfl_xor_sync(0xffffffffu, m1, 2));
    float s0 = 0.f, s1 = 0.f;
    #pragma unroll
    for (int i = 0; i < 16; ++i) {
        p0[i] = __expf(p0[i] - m0); s0 += p0[i];
        p1[i] = __expf(p1[i] - m1); s1 += p1[i];
    }
    s0 += __shfl_xor_sync(0xffffffffu, s0, 1);
    s0 += __shfl_xor_sync(0xffffffffu, s0, 2);
    s1 += __shfl_xor_sync(0xffffffffu, s1, 1);
    s1 += __shfl_xor_sync(0xffffffffu, s1, 2);
    float i0 = __frcp_rn(s0), i1 = __frcp_rn(s1);
    #pragma unroll
    for (int i = 0; i < 16; ++i) { p0[i] *= i0; p1[i] *= i1; }

    // ---- convert P to PV A-fragments in registers (C-frag -> A-frag) ----
    uint32_t pah[4][4], pal[4][4];
    #pragma unroll
    for (int ks = 0; ks < 4; ++ks) {
        pack_hl(p0[4 * ks],     p0[4 * ks + 1], pah[ks][0], pal[ks][0]);
        pack_hl(p1[4 * ks],     p1[4 * ks + 1], pah[ks][1], pal[ks][1]);
        pack_hl(p0[4 * ks + 2], p0[4 * ks + 3], pah[ks][2], pal[ks][2]);
        pack_hl(p1[4 * ks + 2], p1[4 * ks + 3], pah[ks][3], pal[ks][3]);
    }

    // ---- O = P V (16 rows x 32 d-cols per warp) ----
    float oacc[4][4];
    #pragma unroll
    for (int nt = 0; nt < 4; ++nt)
        #pragma unroll
        for (int r = 0; r < 4; ++r) oacc[nt][r] = 0.f;

    #pragma unroll
    for (int ks = 0; ks < 4; ++ks) {
        const int col = ks * 16 + 2 * t;
        #pragma unroll
        for (int nt = 0; nt < 4; ++nt) {
            int ob = (hoff + 8 * nt + g) * VROW + col;
            uint32_t bh[2], bl[2];
            bh[0] = *(const uint32_t*)(svh + ob);
            bh[1] = *(const uint32_t*)(svh + ob + 8);
            bl[0] = *(const uint32_t*)(svl + ob);
            bl[1] = *(const uint32_t*)(svl + ob + 8);
            MMA16816(oacc[nt], pah[ks], bh);
            MMA16816(oacc[nt], pah[ks], bl);
            MMA16816(oacc[nt], pal[ks], bh);
        }
    }

    // ---- store O as bf16 hi/lo ----
    #pragma unroll
    for (int nt = 0; nt < 4; ++nt) {
        int c = hoff + 8 * nt + 2 * t;
        uint32_t hp, lp;
        if (r0 < N_) {
            size_t o = (size_t)(b * N_ + r0) * DIM_ + c;
            pack_hl(oacc[nt][0], oacc[nt][1], hp, lp);
            *(uint32_t*)&oh[o] = hp;
            *(uint32_t*)&ol[o] = lp;
        }
        if (r1 < N_) {
            size_t o = (size_t)(b * N_ + r1) * DIM_ + c;
            pack_hl(oacc[nt][2], oacc[nt][3], hp, lp);
            *(uint32_t*)&oh[o] = hp;
            *(uint32_t*)&ol[o] = lp;
        }
    }
}

// ============================================================================
// launch
// ============================================================================
#define GEMM_SM_BYTES (8 * 128 * 40 * (int)sizeof(__nv_bfloat16))   // 81920
#define ATTN_SM_BYTES (ATTN_SM_ELEMS * (int)sizeof(__nv_bfloat16))  // 106496

extern "C" void kernel_launch(void* const* d_in, const int* in_sizes, int n_in,
                              void* d_out, int out_size)
{
    const float* x      = (const float*)d_in[0];
    const float* mask   = (const float*)d_in[1];
    const float* qkv_w  = (const float*)d_in[2];
    const float* qkv_b  = (const float*)d_in[3];
    const float* proj_w = (const float*)d_in[4];
    const float* proj_b = (const float*)d_in[5];
    const float* rpb    = (const float*)d_in[6];
    const int*   rel    = (const int*)d_in[7];
    float* out = (float*)d_out;

    __nv_bfloat16 *xh, *xl, *qh, *ql, *ohp, *olp, *wqh, *wql, *wph, *wpl;
    float* rmbp;
    cudaGetSymbolAddress((void**)&xh,  g_xh);
    cudaGetSymbolAddress((void**)&xl,  g_xl);
    cudaGetSymbolAddress((void**)&qh,  g_qkvh);
    cudaGetSymbolAddress((void**)&ql,  g_qkvl);
    cudaGetSymbolAddress((void**)&ohp, g_oh);
    cudaGetSymbolAddress((void**)&olp, g_ol);
    cudaGetSymbolAddress((void**)&wqh, g_wqh);
    cudaGetSymbolAddress((void**)&wql, g_wql);
    cudaGetSymbolAddress((void**)&wph, g_wph);
    cudaGetSymbolAddress((void**)&wpl, g_wpl);
    cudaGetSymbolAddress((void**)&rmbp, g_rmb);

    static bool attr_set = false;
    if (!attr_set) {
        cudaFuncSetAttribute(gemm_bf16<true>,  cudaFuncAttributeMaxDynamicSharedMemorySize, GEMM_SM_BYTES);
        cudaFuncSetAttribute(gemm_bf16<false>, cudaFuncAttributeMaxDynamicSharedMemorySize, GEMM_SM_BYTES);
        cudaFuncSetAttribute(attn_mma, cudaFuncAttributeMaxDynamicSharedMemorySize, ATTN_SM_BYTES);
        attr_set = true;
    }

    // setup: conversions + fused mask/rpb table
    convert_x<<<(M_TOTAL * DIM_ / 4) / 256, 256>>>(x);
    convert_w<<<64, 256>>>(qkv_w, proj_w);
    build_rmb<<<N_ * N_, 256>>>(mask, rpb, rel);

    // QKV projection -> bf16 hi/lo
    gemm_bf16<true><<<dim3(QKV_N / 128, M_TOTAL / 128), 256, GEMM_SM_BYTES>>>(
        xh, xl, wqh, wql, qkv_b, nullptr, qh, ql, QKV_N);

    // window attention -> bf16 hi/lo
    attn_mma<<<B_, 512, ATTN_SM_BYTES>>>(qh, ql, rmbp, ohp, olp);

    // output projection -> fp32
    gemm_bf16<false><<<dim3(1, M_TOTAL / 128), 256, GEMM_SM_BYTES>>>(
        ohp, olp, wph, wpl, proj_b, out, nullptr, nullptr, DIM_);
}

// round 7
// speedup vs baseline: 2.7726x; 1.0398x over previous
#include <cuda_runtime.h>
#include <cuda_bf16.h>
#include <math.h>
#include <stdint.h>

// ---------------- problem constants ----------------
#define B_      8192
#define N_      49
#define DIM_    128
#define NH_     4
#define HD_     32
#define NW_     64
#define QKV_N   384
#define M_TOTAL (B_ * N_)          // 401408
#define SCALE_  0.17677669529663687f  // 32^-0.5

// ---------------- scratch (device globals; allocation-free) ----------------
__device__ __nv_bfloat16 g_xh[(size_t)M_TOTAL * DIM_];
__device__ __nv_bfloat16 g_xl[(size_t)M_TOTAL * DIM_];
__device__ __nv_bfloat16 g_qkvh[(size_t)M_TOTAL * QKV_N];
__device__ __nv_bfloat16 g_qkvl[(size_t)M_TOTAL * QKV_N];
__device__ __nv_bfloat16 g_oh[(size_t)M_TOTAL * DIM_];
__device__ __nv_bfloat16 g_ol[(size_t)M_TOTAL * DIM_];
__device__ __nv_bfloat16 g_wqh[QKV_N * DIM_], g_wql[QKV_N * DIM_];
__device__ __nv_bfloat16 g_wph[DIM_ * DIM_], g_wpl[DIM_ * DIM_];
__device__ float g_rmb[NW_ * NH_ * N_ * N_];

// ---------------- helpers ----------------
#define MMA16816(d, a, b)                                                     \
  asm volatile(                                                               \
      "mma.sync.aligned.m16n8k16.row.col.f32.bf16.bf16.f32 "                  \
      "{%0,%1,%2,%3}, {%4,%5,%6,%7}, {%8,%9}, {%0,%1,%2,%3};"                 \
      : "+f"(d[0]), "+f"(d[1]), "+f"(d[2]), "+f"(d[3])                        \
      : "r"(a[0]), "r"(a[1]), "r"(a[2]), "r"(a[3]), "r"(b[0]), "r"(b[1]))

#define LDSM_X4(R0, R1, R2, R3, ADDR)                                         \
  asm volatile("ldmatrix.sync.aligned.m8n8.x4.shared.b16 {%0,%1,%2,%3}, [%4];"\
      : "=r"(R0), "=r"(R1), "=r"(R2), "=r"(R3) : "r"(ADDR))

#define CP_ASYNC_COMMIT asm volatile("cp.async.commit_group;" ::: "memory")
#define CP_ASYNC_WAIT_1 asm volatile("cp.async.wait_group 1;" ::: "memory")
#define CP_ASYNC_WAIT_0 asm volatile("cp.async.wait_group 0;" ::: "memory")

__device__ __forceinline__ void cp16(void* smem, const void* gmem)
{
    uint32_t s = (uint32_t)__cvta_generic_to_shared(smem);
    asm volatile("cp.async.cg.shared.global [%0], [%1], 16;" :: "r"(s), "l"(gmem));
}

__device__ __forceinline__ uint32_t smem_u32(const void* p) {
    uint32_t a;
    asm("{ .reg .u64 t; cvta.to.shared.u64 t, %1; cvt.u32.u64 %0, t; }" : "=r"(a) : "l"(p));
    return a;
}

__device__ __forceinline__ void pack_hl(float a, float b, uint32_t& hp, uint32_t& lp)
{
    __nv_bfloat16 ah = __float2bfloat16(a), bh = __float2bfloat16(b);
    __nv_bfloat16 al = __float2bfloat16(a - __bfloat162float(ah));
    __nv_bfloat16 bl = __float2bfloat16(b - __bfloat162float(bh));
    __nv_bfloat162 hv = __halves2bfloat162(ah, bh);
    __nv_bfloat162 lv = __halves2bfloat162(al, bl);
    hp = *(uint32_t*)&hv;
    lp = *(uint32_t*)&lv;
}

// ============================================================================
// setup kernels
// ============================================================================
__global__ void convert_x(const float* __restrict__ x)
{
    size_t i = (size_t)blockIdx.x * 256 + threadIdx.x;
    float4 v = ((const float4*)x)[i];
    uint32_t h0, l0, h1, l1;
    pack_hl(v.x, v.y, h0, l0);
    pack_hl(v.z, v.w, h1, l1);
    ((uint2*)g_xh)[i] = make_uint2(h0, h1);
    ((uint2*)g_xl)[i] = make_uint2(l0, l1);
}

__global__ void convert_w(const float* __restrict__ qkv_w, const float* __restrict__ proj_w)
{
    int i = blockIdx.x * 256 + threadIdx.x;
    float4 v;
    if (i < 12288) v = ((const float4*)qkv_w)[i];
    else           v = ((const float4*)proj_w)[i - 12288];
    uint32_t h0, l0, h1, l1;
    pack_hl(v.x, v.y, h0, l0);
    pack_hl(v.z, v.w, h1, l1);
    if (i < 12288) {
        ((uint2*)g_wqh)[i] = make_uint2(h0, h1);
        ((uint2*)g_wql)[i] = make_uint2(l0, l1);
    } else {
        ((uint2*)g_wph)[i - 12288] = make_uint2(h0, h1);
        ((uint2*)g_wpl)[i - 12288] = make_uint2(l0, l1);
    }
}

__global__ void build_rmb(const float* __restrict__ mask, const float* __restrict__ rpb,
                          const int* __restrict__ rel)
{
    int t = blockIdx.x * 256 + threadIdx.x;
    int ij = t % (N_ * N_);
    int wh = t / (N_ * N_);
    int h = wh & 3, w = wh >> 2;
    g_rmb[t] = mask[w * N_ * N_ + ij] + rpb[rel[ij] * NH_ + h];
}

// ============================================================================
// Split-bf16 HMMA GEMM with ldmatrix fragment loads.
// out = A @ B^T + bias; A,B fp32 pre-split into hi/lo bf16.
// CTA 128x128, k-chunk 32, 2-stage cp.async pipeline, 256 thr, 2 CTA/SM.
// ============================================================================
template<bool OUT_BF16>
__global__ void __launch_bounds__(256, 2) gemm_bf16(
    const __nv_bfloat16* __restrict__ Ahg, const __nv_bfloat16* __restrict__ Alg,
    const __nv_bfloat16* __restrict__ Bhg, const __nv_bfloat16* __restrict__ Blg,
    const float* __restrict__ bias,
    float* __restrict__ outf, __nv_bfloat16* __restrict__ outh,
    __nv_bfloat16* __restrict__ outl, int Nstride)
{
    extern __shared__ __align__(16) __nv_bfloat16 sm[];
    const int STG = 128 * 40;                 // one stage slab (elems)
    __nv_bfloat16* sAh = sm;                  // [2][128][40]
    __nv_bfloat16* sAl = sm + 2 * STG;
    __nv_bfloat16* sBh = sm + 4 * STG;
    __nv_bfloat16* sBl = sm + 6 * STG;

    const int tid  = threadIdx.x;
    const int lane = tid & 31;
    const int warp = tid >> 5;
    const int wm   = warp & 3;
    const int wn   = warp >> 2;
    const int g    = lane >> 2;
    const int t    = lane & 3;

    const int m0 = blockIdx.y * 128;
    const int n0 = blockIdx.x * 128;

    // ldmatrix per-lane byte offsets (within one array; stage/ks added later)
    const uint32_t uAh = smem_u32(sAh), uAl = smem_u32(sAl);
    const uint32_t uBh = smem_u32(sBh), uBl = smem_u32(sBl);
    const uint32_t aOff = ((wm * 32 + (lane & 7) + ((lane >> 3) & 1) * 8) * 40
                           + ((lane >> 4) & 1) * 8) * 2;
    const uint32_t bOff = ((wn * 64 + (lane & 7) + ((lane >> 4) & 1) * 8) * 40
                           + ((lane >> 3) & 1) * 8) * 2;

    float acc[2][8][4];
    #pragma unroll
    for (int mt = 0; mt < 2; ++mt)
        #pragma unroll
        for (int nt = 0; nt < 8; ++nt)
            #pragma unroll
            for (int r = 0; r < 4; ++r) acc[mt][nt][r] = 0.f;

    auto load_stage = [&](int st, int kc) {
        #pragma unroll
        for (int it = 0; it < 2; ++it) {
            int idx = tid + it * 256;            // 0..511
            int row = idx >> 2;                  // 0..127
            int c8  = (idx & 3) * 8;             // 0,8,16,24
            size_t gA = (size_t)(m0 + row) * DIM_ + kc + c8;
            size_t gB = (size_t)(n0 + row) * DIM_ + kc + c8;
            int so = st * STG + row * 40 + c8;
            cp16(sAh + so, Ahg + gA);
            cp16(sAl + so, Alg + gA);
            cp16(sBh + so, Bhg + gB);
            cp16(sBl + so, Blg + gB);
        }
    };

    load_stage(0, 0);  CP_ASYNC_COMMIT;
    load_stage(1, 32); CP_ASYNC_COMMIT;

    for (int c = 0; c < 4; ++c) {
        if (c < 3) { CP_ASYNC_WAIT_1; } else { CP_ASYNC_WAIT_0; }
        __syncthreads();

        const uint32_t stB = (uint32_t)((c & 1) * (STG * 2));   // stage byte offset
        #pragma unroll
        for (int ks = 0; ks < 2; ++ks) {
            const uint32_t kB = stB + ks * 32;   // ks*16 elems = 32 bytes
            uint32_t afh[2][4], afl[2][4];
            LDSM_X4(afh[0][0], afh[0][1], afh[0][2], afh[0][3], uAh + kB + aOff);
            LDSM_X4(afh[1][0], afh[1][1], afh[1][2], afh[1][3], uAh + kB + aOff + 1280);
            LDSM_X4(afl[0][0], afl[0][1], afl[0][2], afl[0][3], uAl + kB + aOff);
            LDSM_X4(afl[1][0], afl[1][1], afl[1][2], afl[1][3], uAl + kB + aOff + 1280);

            #pragma unroll
            for (int half = 0; half < 2; ++half) {
                uint32_t bh[4][2], bl[4][2];
                #pragma unroll
                for (int p = 0; p < 2; ++p) {
                    uint32_t ba = kB + bOff + (uint32_t)((half * 2 + p) * 1280);
                    LDSM_X4(bh[2*p][0], bh[2*p][1], bh[2*p+1][0], bh[2*p+1][1], uBh + ba);
                    LDSM_X4(bl[2*p][0], bl[2*p][1], bl[2*p+1][0], bl[2*p+1][1], uBl + ba);
                }
                #pragma unroll
                for (int q = 0; q < 4; ++q) {
                    int nt = half * 4 + q;
                    #pragma unroll
                    for (int mt = 0; mt < 2; ++mt) {
                        MMA16816(acc[mt][nt], afh[mt], bh[q]);
                        MMA16816(acc[mt][nt], afh[mt], bl[q]);
                        MMA16816(acc[mt][nt], afl[mt], bh[q]);
                    }
                }
            }
        }
        __syncthreads();
        if (c < 2) { load_stage(c & 1, (c + 2) * 32); CP_ASYNC_COMMIT; }
    }

    // ---- epilogue ----
    #pragma unroll
    for (int mt = 0; mt < 2; ++mt) {
        int r0 = m0 + wm * 32 + mt * 16 + g;
        #pragma unroll
        for (int nt = 0; nt < 8; ++nt) {
            int cc = n0 + wn * 64 + nt * 8 + 2 * t;
            float b0 = __ldg(&bias[cc]);
            float b1 = __ldg(&bias[cc + 1]);
            float v00 = acc[mt][nt][0] + b0, v01 = acc[mt][nt][1] + b1;
            float v10 = acc[mt][nt][2] + b0, v11 = acc[mt][nt][3] + b1;
            if (OUT_BF16) {
                uint32_t hp, lp;
                pack_hl(v00, v01, hp, lp);
                *(uint32_t*)&outh[(size_t)r0 * Nstride + cc] = hp;
                *(uint32_t*)&outl[(size_t)r0 * Nstride + cc] = lp;
                pack_hl(v10, v11, hp, lp);
                *(uint32_t*)&outh[(size_t)(r0 + 8) * Nstride + cc] = hp;
                *(uint32_t*)&outl[(size_t)(r0 + 8) * Nstride + cc] = lp;
            } else {
                *(float2*)&outf[(size_t)r0 * Nstride + cc] = make_float2(v00, v01);
                *(float2*)&outf[(size_t)(r0 + 8) * Nstride + cc] = make_float2(v10, v11);
            }
        }
    }
}

// ============================================================================
// Register-resident MMA window attention, ldmatrix fragment loads.
// One CTA/window, 512 threads (16 warps). warp -> (head = w>>2, mtile = w&3).
// ============================================================================
#define QROW 136            // q/k smem row stride (bf16)
#define VROW 72             // vT smem row stride
#define ASM_Q (64 * QROW)
#define ASM_V (128 * VROW)
#define ATTN_SM_ELEMS (4 * ASM_Q + 2 * ASM_V)

__global__ void __launch_bounds__(512) attn_mma(
    const __nv_bfloat16* __restrict__ qkvh, const __nv_bfloat16* __restrict__ qkvl,
    const float* __restrict__ rmb,
    __nv_bfloat16* __restrict__ oh, __nv_bfloat16* __restrict__ ol)
{
    extern __shared__ __align__(16) __nv_bfloat16 sm[];
    __nv_bfloat16* sqh = sm;
    __nv_bfloat16* sql = sm + ASM_Q;
    __nv_bfloat16* skh = sm + 2 * ASM_Q;
    __nv_bfloat16* skl = sm + 3 * ASM_Q;
    __nv_bfloat16* svh = sm + 4 * ASM_Q;
    __nv_bfloat16* svl = sm + 4 * ASM_Q + ASM_V;

    const int b    = blockIdx.x;
    const int tid  = threadIdx.x;
    const int lane = tid & 31;
    const int warp = tid >> 5;
    const int g    = lane >> 2;
    const int t    = lane & 3;
    const int h    = warp >> 2;
    const int wm   = warp & 3;

    {
        uint4 zz = make_uint4(0, 0, 0, 0);
        uint4* zp = (uint4*)sm;
        #pragma unroll 4
        for (int i = tid; i < ATTN_SM_ELEMS / 8; i += 512) zp[i] = zz;
    }
    __syncthreads();

    for (int idx = tid; idx < 49 * 16; idx += 512) {
        int i = idx >> 4, seg = (idx & 15) * 8;
        size_t gb = (size_t)(b * N_ + i) * QKV_N + seg;
        cp16(sqh + i * QROW + seg, qkvh + gb);
        cp16(sql + i * QROW + seg, qkvl + gb);
        cp16(skh + i * QROW + seg, qkvh + gb + 128);
        cp16(skl + i * QROW + seg, qkvl + gb + 128);
    }
    for (int idx = tid; idx < 49 * 64; idx += 512) {
        int dp = idx & 63, i = idx >> 6;
        size_t gb = (size_t)(b * N_ + i) * QKV_N + 256 + 2 * dp;
        uint32_t vh = *(const uint32_t*)(qkvh + gb);
        uint32_t vl = *(const uint32_t*)(qkvl + gb);
        int d0 = 2 * dp;
        ((uint16_t*)svh)[d0 * VROW + i]       = (uint16_t)(vh & 0xffff);
        ((uint16_t*)svh)[(d0 + 1) * VROW + i] = (uint16_t)(vh >> 16);
        ((uint16_t*)svl)[d0 * VROW + i]       = (uint16_t)(vl & 0xffff);
        ((uint16_t*)svl)[(d0 + 1) * VROW + i] = (uint16_t)(vl >> 16);
    }
    CP_ASYNC_COMMIT; CP_ASYNC_WAIT_0;
    __syncthreads();

    const int hoff = h * HD_;
    const int r0 = 16 * wm + g;
    const int r1 = r0 + 8;

    // ldmatrix per-lane byte offsets
    const uint32_t uqh = smem_u32(sqh), uql = smem_u32(sql);
    const uint32_t ukh = smem_u32(skh), ukl = smem_u32(skl);
    const uint32_t uvh = smem_u32(svh), uvl = smem_u32(svl);
    const uint32_t qaOff = ((16 * wm + (lane & 7) + ((lane >> 3) & 1) * 8) * QROW
                            + hoff + ((lane >> 4) & 1) * 8) * 2;
    const uint32_t kbOff = (((lane & 7) + ((lane >> 4) & 1) * 8) * QROW
                            + hoff + ((lane >> 3) & 1) * 8) * 2;
    const uint32_t vbOff = ((hoff + (lane & 7) + ((lane >> 4) & 1) * 8) * VROW
                            + ((lane >> 3) & 1) * 8) * 2;

    // ---- S = Q K^T ----
    float sacc[8][4];
    #pragma unroll
    for (int nt = 0; nt < 8; ++nt)
        #pragma unroll
        for (int r = 0; r < 4; ++r) sacc[nt][r] = 0.f;

    #pragma unroll
    for (int ks = 0; ks < 2; ++ks) {
        const uint32_t kB = ks * 32;
        uint32_t ah[4], al[4];
        LDSM_X4(ah[0], ah[1], ah[2], ah[3], uqh + qaOff + kB);
        LDSM_X4(al[0], al[1], al[2], al[3], uql + qaOff + kB);
        #pragma unroll
        for (int p = 0; p < 4; ++p) {
            uint32_t bh[2][2], bl[2][2];
            uint32_t ba = kbOff + kB + (uint32_t)(p * 16 * QROW * 2);
            LDSM_X4(bh[0][0], bh[0][1], bh[1][0], bh[1][1], ukh + ba);
            LDSM_X4(bl[0][0], bl[0][1], bl[1][0], bl[1][1], ukl + ba);
            MMA16816(sacc[2*p],     ah, bh[0]);
            MMA16816(sacc[2*p],     ah, bl[0]);
            MMA16816(sacc[2*p],     al, bh[0]);
            MMA16816(sacc[2*p + 1], ah, bh[1]);
            MMA16816(sacc[2*p + 1], ah, bl[1]);
            MMA16816(sacc[2*p + 1], al, bh[1]);
        }
    }

    // ---- bias + mask, register softmax (quad shuffles) ----
    const float* rmbw = rmb + (((b & (NW_ - 1)) * NH_ + h) * N_ * N_);
    float p0[16], p1[16];
    #pragma unroll
    for (int nt = 0; nt < 8; ++nt) {
        int c0 = 8 * nt + 2 * t;
        int c1 = c0 + 1;
        p0[2 * nt]     = (r0 < N_ && c0 < N_) ? fmaf(sacc[nt][0], SCALE_, __ldg(rmbw + r0 * N_ + c0)) : -1e30f;
        p0[2 * nt + 1] = (r0 < N_ && c1 < N_) ? fmaf(sacc[nt][1], SCALE_, __ldg(rmbw + r0 * N_ + c1)) : -1e30f;
        p1[2 * nt]     = (r1 < N_ && c0 < N_) ? fmaf(sacc[nt][2], SCALE_, __ldg(rmbw + r1 * N_ + c0)) : -1e30f;
        p1[2 * nt + 1] = (r1 < N_ && c1 < N_) ? fmaf(sacc[nt][3], SCALE_, __ldg(rmbw + r1 * N_ + c1)) : -1e30f;
    }
    float m0 = -1e30f, m1 = -1e30f;
    #pragma unroll
    for (int i = 0; i < 16; ++i) { m0 = fmaxf(m0, p0[i]); m1 = fmaxf(m1, p1[i]); }
    m0 = fmaxf(m0, __shfl_xor_sync(0xffffffffu, m0, 1));
    m0 = fmaxf(m0, __shfl_xor_sync(0xffffffffu, m0, 2));
    m1 = fmaxf(m1, __shfl_xor_sync(0xffffffffu, m1, 1));
    m1 = fmaxf(m1, __shfl_xor_sync(0xffffffffu, m1, 2));
    float s0 = 0.f, s1 = 0.f;
    #pragma unroll
    for (int i = 0; i < 16; ++i) {
        p0[i] = __expf(p0[i] - m0); s0 += p0[i];
        p1[i] = __expf(p1[i] - m1); s1 += p1[i];
    }
    s0 += __shfl_xor_sync(0xffffffffu, s0, 1);
    s0 += __shfl_xor_sync(0xffffffffu, s0, 2);
    s1 += __shfl_xor_sync(0xffffffffu, s1, 1);
    s1 += __shfl_xor_sync(0xffffffffu, s1, 2);
    float i0 = __frcp_rn(s0), i1 = __frcp_rn(s1);
    #pragma unroll
    for (int i = 0; i < 16; ++i) { p0[i] *= i0; p1[i] *= i1; }

    // ---- P -> PV A-fragments in registers ----
    uint32_t pah[4][4], pal[4][4];
    #pragma unroll
    for (int ks = 0; ks < 4; ++ks) {
        pack_hl(p0[4 * ks],     p0[4 * ks + 1], pah[ks][0], pal[ks][0]);
        pack_hl(p1[4 * ks],     p1[4 * ks + 1], pah[ks][1], pal[ks][1]);
        pack_hl(p0[4 * ks + 2], p0[4 * ks + 3], pah[ks][2], pal[ks][2]);
        pack_hl(p1[4 * ks + 2], p1[4 * ks + 3], pah[ks][3], pal[ks][3]);
    }

    // ---- O = P V ----
    float oacc[4][4];
    #pragma unroll
    for (int nt = 0; nt < 4; ++nt)
        #pragma unroll
        for (int r = 0; r < 4; ++r) oacc[nt][r] = 0.f;

    #pragma unroll
    for (int ks = 0; ks < 4; ++ks) {
        const uint32_t kB = ks * 32;
        #pragma unroll
        for (int p = 0; p < 2; ++p) {
            uint32_t bh[2][2], bl[2][2];
            uint32_t ba = vbOff + kB + (uint32_t)(p * 16 * VROW * 2);
            LDSM_X4(bh[0][0], bh[0][1], bh[1][0], bh[1][1], uvh + ba);
            LDSM_X4(bl[0][0], bl[0][1], bl[1][0], bl[1][1], uvl + ba);
            MMA16816(oacc[2*p],     pah[ks], bh[0]);
            MMA16816(oacc[2*p],     pah[ks], bl[0]);
            MMA16816(oacc[2*p],     pal[ks], bh[0]);
            MMA16816(oacc[2*p + 1], pah[ks], bh[1]);
            MMA16816(oacc[2*p + 1], pah[ks], bl[1]);
            MMA16816(oacc[2*p + 1], pal[ks], bh[1]);
        }
    }

    // ---- store O as bf16 hi/lo ----
    #pragma unroll
    for (int nt = 0; nt < 4; ++nt) {
        int c = hoff + 8 * nt + 2 * t;
        uint32_t hp, lp;
        if (r0 < N_) {
            size_t o = (size_t)(b * N_ + r0) * DIM_ + c;
            pack_hl(oacc[nt][0], oacc[nt][1], hp, lp);
            *(uint32_t*)&oh[o] = hp;
            *(uint32_t*)&ol[o] = lp;
        }
        if (r1 < N_) {
            size_t o = (size_t)(b * N_ + r1) * DIM_ + c;
            pack_hl(oacc[nt][2], oacc[nt][3], hp, lp);
            *(uint32_t*)&oh[o] = hp;
            *(uint32_t*)&ol[o] = lp;
        }
    }
}

// ============================================================================
// launch
// ============================================================================
#define GEMM_SM_BYTES (8 * 128 * 40 * (int)sizeof(__nv_bfloat16))   // 81920
#define ATTN_SM_BYTES (ATTN_SM_ELEMS * (int)sizeof(__nv_bfloat16))  // 106496

extern "C" void kernel_launch(void* const* d_in, const int* in_sizes, int n_in,
                              void* d_out, int out_size)
{
    const float* x      = (const float*)d_in[0];
    const float* mask   = (const float*)d_in[1];
    const float* qkv_w  = (const float*)d_in[2];
    const float* qkv_b  = (const float*)d_in[3];
    const float* proj_w = (const float*)d_in[4];
    const float* proj_b = (const float*)d_in[5];
    const float* rpb    = (const float*)d_in[6];
    const int*   rel    = (const int*)d_in[7];
    float* out = (float*)d_out;

    __nv_bfloat16 *xh, *xl, *qh, *ql, *ohp, *olp, *wqh, *wql, *wph, *wpl;
    float* rmbp;
    cudaGetSymbolAddress((void**)&xh,  g_xh);
    cudaGetSymbolAddress((void**)&xl,  g_xl);
    cudaGetSymbolAddress((void**)&qh,  g_qkvh);
    cudaGetSymbolAddress((void**)&ql,  g_qkvl);
    cudaGetSymbolAddress((void**)&ohp, g_oh);
    cudaGetSymbolAddress((void**)&olp, g_ol);
    cudaGetSymbolAddress((void**)&wqh, g_wqh);
    cudaGetSymbolAddress((void**)&wql, g_wql);
    cudaGetSymbolAddress((void**)&wph, g_wph);
    cudaGetSymbolAddress((void**)&wpl, g_wpl);
    cudaGetSymbolAddress((void**)&rmbp, g_rmb);

    static bool attr_set = false;
    if (!attr_set) {
        cudaFuncSetAttribute(gemm_bf16<true>,  cudaFuncAttributeMaxDynamicSharedMemorySize, GEMM_SM_BYTES);
        cudaFuncSetAttribute(gemm_bf16<false>, cudaFuncAttributeMaxDynamicSharedMemorySize, GEMM_SM_BYTES);
        cudaFuncSetAttribute(attn_mma, cudaFuncAttributeMaxDynamicSharedMemorySize, ATTN_SM_BYTES);
        attr_set = true;
    }

    convert_x<<<(M_TOTAL * DIM_ / 4) / 256, 256>>>(x);
    convert_w<<<64, 256>>>(qkv_w, proj_w);
    build_rmb<<<N_ * N_, 256>>>(mask, rpb, rel);

    // QKV projection -> bf16 hi/lo
    gemm_bf16<true><<<dim3(QKV_N / 128, M_TOTAL / 128), 256, GEMM_SM_BYTES>>>(
        xh, xl, wqh, wql, qkv_b, nullptr, qh, ql, QKV_N);

    // window attention -> bf16 hi/lo
    attn_mma<<<B_, 512, ATTN_SM_BYTES>>>(qh, ql, rmbp, ohp, olp);

    // output projection -> fp32
    gemm_bf16<false><<<dim3(1, M_TOTAL / 128), 256, GEMM_SM_BYTES>>>(
        ohp, olp, wph, wpl, proj_b, out, nullptr, nullptr, DIM_);
}